// round 17
// baseline (speedup 1.0000x reference)
#include <cuda_runtime.h>

// Fixed shapes: B=2, D=1024, L=2048, NH=8 -> H=128
#define B_   2
#define D_   1024
#define L_   2048
#define NH   8
#define H_   128
#define TLL  256          // l-tile per block: 128 threads x 2 l (l0=L0+2t, l1=l0+1)
#define TMX  256          // m-tile
#define KR2  2720         // padded reversed-filter row length
#define KWIN 520          // k smem window floats per stage
#define NST  2            // pipeline stages

typedef unsigned long long u64;

// Reversed zero-padded filter: g_kra[h][u] = kval(h, 2306 - u),
// where kval(h,a) = k[h][a] for 0<=a<L, else 0.
__device__ __align__(16) float g_kra[H_ * KR2];

__device__ __forceinline__ u64 pack2(float x, float y) {
    u64 r; asm("mov.b64 %0, {%1,%2};" : "=l"(r) : "f"(x), "f"(y)); return r;
}
__device__ __forceinline__ float lo2(u64 v) {
    float x, y; asm("mov.b64 {%0,%1}, %2;" : "=f"(x), "=f"(y) : "l"(v)); return x;
}
__device__ __forceinline__ float hi2(u64 v) {
    float x, y; asm("mov.b64 {%0,%1}, %2;" : "=f"(x), "=f"(y) : "l"(v)); return y;
}
__device__ __forceinline__ float hsum2(u64 v) {
    float x, y; asm("mov.b64 {%0,%1}, %2;" : "=f"(x), "=f"(y) : "l"(v)); return x + y;
}
__device__ __forceinline__ u64 fma2(u64 a, u64 b, u64 c) {
    u64 d; asm("fma.rn.f32x2 %0, %1, %2, %3;" : "=l"(d) : "l"(a), "l"(b), "l"(c)); return d;
}
__device__ __forceinline__ u64 mul2(u64 a, u64 b) {
    u64 d; asm("mul.rn.f32x2 %0, %1, %2;" : "=l"(d) : "l"(a), "l"(b)); return d;
}
__device__ __forceinline__ u64 ll(double d) { return __double_as_longlong(d); }
__device__ __forceinline__ void cpasync16(void* dst, const void* src) {
    unsigned d = (unsigned)__cvta_generic_to_shared(dst);
    asm volatile("cp.async.ca.shared.global [%0], [%1], 16;" :: "r"(d), "l"(src));
}

__global__ void build_kr(const float* __restrict__ k) {
    int idx = blockIdx.x * 256 + threadIdx.x;
    if (idx >= H_ * KR2) return;
    int h = idx / KR2, u = idx % KR2;
    int a = (L_ + 258) - u;        // 2306 - u
    g_kra[idx] = (a >= 0 && a < L_) ? k[h * L_ + a] : 0.0f;
}

// Tile body. MM must be a multiple of 32 (unroll 8 x 4m, no remainder).
// A-lane taps: two aligned LDS.64 (proven-correct R15 form). B-lane taps
// derived from tap registers via a 1-value loop carry (kbp[s] == kap[s-1]).
#define COMPUTE_TILE(MM)                                                     \
    u64 kpn = *(const u64*)(kap - 2);                                        \
    _Pragma("unroll 8")                                                      \
    for (int mm = 0; mm < (MM); mm += 4) {                                   \
        u64 kc = *(const u64*)(kap + mm);                                    \
        u64 kn = *(const u64*)(kap + mm + 2);                                \
        u64 sA0, sA1, sB0, sB1;                                              \
        {                                                                    \
            double2 vq = *(const double2*)&vt[0][mm];                        \
            u64 vlo = ll(vq.x), vhi = ll(vq.y);                              \
            sA0 = mul2(x1A[0], vlo); sA1 = mul2(x1A[0], vhi);                \
            sB0 = mul2(x1B[0], vlo); sB1 = mul2(x1B[0], vhi);                \
        }                                                                    \
        _Pragma("unroll")                                                    \
        for (int i = 1; i < NH; i++) {                                       \
            double2 vq = *(const double2*)&vt[i][mm];                        \
            u64 vlo = ll(vq.x), vhi = ll(vq.y);                              \
            sA0 = fma2(x1A[i], vlo, sA0); sA1 = fma2(x1A[i], vhi, sA1);      \
            sB0 = fma2(x1B[i], vlo, sB0); sB1 = fma2(x1B[i], vhi, sB1);      \
        }                                                                    \
        u64 tA0 = mul2(kc, sA0);                                             \
        u64 tA1 = mul2(kn, sA1);                                             \
        u64 tB0 = mul2(pack2(hi2(kpn), lo2(kc)), sB0);                       \
        u64 tB1 = mul2(pack2(hi2(kc),  lo2(kn)), sB1);                       \
        kpn = kn;                                                            \
        _Pragma("unroll")                                                    \
        for (int j = 0; j < NH; j++) {                                       \
            double2 xq = *(const double2*)&x2t[j][mm];                       \
            u64 xlo = ll(xq.x), xhi = ll(xq.y);                              \
            accA[j] = fma2(tA0, xlo, accA[j]);                               \
            accB[j] = fma2(tB0, xlo, accB[j]);                               \
            accA[j] = fma2(tA1, xhi, accA[j]);                               \
            accB[j] = fma2(tB1, xhi, accB[j]);                               \
        }                                                                    \
    }

__global__ void __launch_bounds__(128, 5)
hyena_conv_kernel(const float* __restrict__ v,
                  const float* __restrict__ bias,
                  const float* __restrict__ x1,
                  const float* __restrict__ x2,
                  float* __restrict__ out)
{
    __shared__ __align__(16) float vsm [NST][NH][TMX];
    __shared__ __align__(16) float x2sm[NST][NH][TMX];
    __shared__ __align__(16) float wa[NST][KWIN];
    __shared__ float bsm[NH];

    const int tid = threadIdx.x;
    const int wid = tid >> 5;
    const int blk = blockIdx.x;
    const int bh  = blk & 255;
    const int lt  = 7 - (blk >> 8);       // LPT: heavy l-tiles first
    const int h   = bh & 127;
    const int b   = bh >> 7;
    const int L0  = lt * TLL;
    const int l0  = L0 + 2 * tid;

    const float* vb  = v  + ((size_t)b * D_ + (size_t)h * NH) * L_;
    const float* x1b = x1 + ((size_t)b * D_ + (size_t)h * NH) * L_;
    const float* x2b = x2 + ((size_t)b * D_ + (size_t)h * NH) * L_;
    float*       ob  = out + ((size_t)b * D_ + (size_t)h * NH) * L_;
    const float* kra = g_kra + (size_t)h * KR2;

    const int nmt = lt + 1;               // m-tiles (TMX=256): 1..8

    auto issue = [&](int mt_, int p) {
        const int M0 = mt_ * TMX;
        #pragma unroll
        for (int q = 0; q < 4; q++) {
            int f = tid + 128 * q;                 // 0..511 chunk id
            int i = f >> 6, c = (f & 63) << 2;
            cpasync16(&vsm [p][i][c], vb  + i * L_ + M0 + c);
            cpasync16(&x2sm[p][i][c], x2b + i * L_ + M0 + c);
        }
        const int u0 = L_ - L0 + M0;               // >= 256, u0+519 < KR2
        cpasync16(&wa[p][tid * 4], kra + u0 + tid * 4);
        if (tid < 2) cpasync16(&wa[p][(128 + tid) * 4], kra + u0 + (128 + tid) * 4);
        asm volatile("cp.async.commit_group;" ::: "memory");
    };

    issue(0, 0);

    if (tid < NH) bsm[tid] = bias[h * NH + tid];

    // x1 gate splats for l0, l1
    u64 x1A[NH], x1B[NH];
    #pragma unroll
    for (int i = 0; i < NH; i++) {
        float2 q = *(const float2*)&x1b[i * L_ + l0];
        x1A[i] = pack2(q.x, q.x);
        x1B[i] = pack2(q.y, q.y);
    }

    u64 accA[NH], accB[NH];
    #pragma unroll
    for (int j = 0; j < NH; j++) { accA[j] = 0; accB[j] = 0; }

    const int soff = 258 - 2 * tid;       // taps: kap[mm] = kval(l0 - M0 - mm)

    for (int mt = 0; mt < nmt; mt++) {
        asm volatile("cp.async.wait_group 0;" ::: "memory");
        __syncthreads();

        // stage (mt+1)&1 was consumed at tile mt-1 (fenced by the barrier above):
        // issue next tile before compute so the load overlaps this tile fully.
        if (mt + 1 < nmt) issue(mt + 1, (mt + 1) & 1);

        const int p = mt & 1;
        const float (*vt)[TMX]  = vsm[p];
        const float (*x2t)[TMX] = x2sm[p];
        const float* kap = &wa[p][soff];

        if (mt < nmt - 1) {
            // interior tile: always full, compile-time trip count 64
            COMPUTE_TILE(TMX)
        } else {
            // diagonal tile (base = 0): per-warp triangular bound, multiple of 64
            const int mmaxw = 64 * wid + 64;
            COMPUTE_TILE(mmaxw)
        }
    }

    // Epilogue: horizontal add + skip/bias term, float2 stores.
    float sbA = 0.f, sbB = 0.f;
    #pragma unroll
    for (int i = 0; i < NH; i++) {
        float2 vv = *(const float2*)&vb[i * L_ + l0];
        float bw = bsm[i];
        sbA += lo2(x1A[i]) * bw * vv.x;
        sbB += lo2(x1B[i]) * bw * vv.y;
    }
    #pragma unroll
    for (int j = 0; j < NH; j++) {
        float2 xx = *(const float2*)&x2b[j * L_ + l0];
        float2 o;
        o.x = hsum2(accA[j]) + sbA * xx.x;
        o.y = hsum2(accB[j]) + sbB * xx.y;
        *(float2*)&ob[j * L_ + l0] = o;
    }
}

extern "C" void kernel_launch(void* const* d_in, const int* in_sizes, int n_in,
                              void* d_out, int out_size)
{
    const float* v    = (const float*)d_in[0];
    const float* k    = (const float*)d_in[1];
    const float* bias = (const float*)d_in[2];
    const float* x1   = (const float*)d_in[3];
    const float* x2   = (const float*)d_in[4];
    float* out = (float*)d_out;

    build_kr<<<(H_ * KR2 + 255) / 256, 256>>>(k);
    dim3 grid(B_ * H_ * (L_ / TLL));   // 2048 blocks, heavy l-tiles first
    hyena_conv_kernel<<<grid, 128>>>(v, bias, x1, x2, out);
}